// round 1
// baseline (speedup 1.0000x reference)
#include <cuda_runtime.h>

// Problem constants
#define B_ 8
#define C_ 512
#define N_ 4096
#define E_ 1024
#define H_ 8
#define D_ 128

// Scratch (device globals; allocation-free per harness rules). ~52 MB total.
__device__ float d_G  [B_ * C_ * C_];   // Gram matrices x xT        (8 MB)
__device__ float d_s  [B_ * C_];        // row sums of x
__device__ float d_t  [B_ * 3 * E_];    // W_qkv @ s
__device__ float d_A1 [B_ * E_ * C_];   // Wq @ G                    (16 MB)
__device__ float d_att[B_ * H_ * D_ * D_]; // logits -> probs        (4 MB)
__device__ float d_M  [B_ * E_ * C_];   // att @ Wv                  (16 MB)
__device__ float d_cv [B_ * E_];        // att @ bv
__device__ float d_F  [B_ * C_ * C_];   // w_out @ M                 (8 MB)
__device__ float d_g  [B_ * C_];        // w_out @ cv + b_out

// ---------------------------------------------------------------------------
// Generic tiled fp32 GEMM: C[z] = A[z] (MxK) * op(B[z]) (KxN) [+ bias[z][row]]
// TRANSB=false: B is (K,N) row-major.  TRANSB=true: B is (N,K) row-major.
// Per-z offsets: zo=z/ZB, zi=z%ZB; ptr += zo*s?o + zi*s?i. C offset = z*sCo.
// Tile 128x128, BK=16, 256 threads, 8x8 per thread. M,N multiples of 128 (or
// exactly equal to grid*128), K multiple of 16 — guaranteed by launch params.
// ---------------------------------------------------------------------------
#define BM 128
#define BN 128
#define BK 16

template <bool TRANSB>
__global__ void __launch_bounds__(256)
sgemm(const float* __restrict__ A, const float* __restrict__ B,
      float* __restrict__ C, const float* __restrict__ bias,
      int K, int lda, int ldb, int ldc,
      long long sAo, long long sAi, long long sBo, long long sBi,
      long long sCo, long long sBias, int ZB)
{
    const int z  = blockIdx.z;
    const int zo = z / ZB;
    const int zi = z - zo * ZB;
    A += zo * sAo + zi * sAi;
    B += zo * sBo + zi * sBi;
    C += (long long)z * sCo;

    __shared__ float As[BK][BM + 4];
    __shared__ float Bs[BK][BN + 4];

    const int tid  = threadIdx.x;
    const int tx   = tid & 15;
    const int ty   = tid >> 4;
    const int row0 = blockIdx.y * BM;
    const int col0 = blockIdx.x * BN;

    const int lr = tid >> 2;         // 0..63
    const int lc = (tid & 3) * 4;    // 0,4,8,12

    float acc[8][8];
#pragma unroll
    for (int i = 0; i < 8; i++)
#pragma unroll
        for (int j = 0; j < 8; j++) acc[i][j] = 0.f;

    for (int kk = 0; kk < K; kk += BK) {
        // Load A tile (BM x BK), store transposed
#pragma unroll
        for (int it = 0; it < 2; it++) {
            int r = lr + it * 64;
            float4 v = *(const float4*)&A[(long long)(row0 + r) * lda + kk + lc];
            As[lc + 0][r] = v.x; As[lc + 1][r] = v.y;
            As[lc + 2][r] = v.z; As[lc + 3][r] = v.w;
        }
        if (TRANSB) {
            // B is (N,K): load rows of B-tile, store transposed into Bs[k][j]
#pragma unroll
            for (int it = 0; it < 2; it++) {
                int r = lr + it * 64;
                float4 v = *(const float4*)&B[(long long)(col0 + r) * ldb + kk + lc];
                Bs[lc + 0][r] = v.x; Bs[lc + 1][r] = v.y;
                Bs[lc + 2][r] = v.z; Bs[lc + 3][r] = v.w;
            }
        } else {
            // B is (K,N): straight copy
#pragma unroll
            for (int it = 0; it < 2; it++) {
                int f = tid + it * 256;
                int k = f >> 5;
                int j = (f & 31) * 4;
                *(float4*)&Bs[k][j] =
                    *(const float4*)&B[(long long)(kk + k) * ldb + col0 + j];
            }
        }
        __syncthreads();

#pragma unroll
        for (int k = 0; k < BK; k++) {
            float4 a0 = *(const float4*)&As[k][ty * 8];
            float4 a1 = *(const float4*)&As[k][ty * 8 + 4];
            float4 b0 = *(const float4*)&Bs[k][tx * 8];
            float4 b1 = *(const float4*)&Bs[k][tx * 8 + 4];
            float av[8] = {a0.x, a0.y, a0.z, a0.w, a1.x, a1.y, a1.z, a1.w};
            float bv[8] = {b0.x, b0.y, b0.z, b0.w, b1.x, b1.y, b1.z, b1.w};
#pragma unroll
            for (int i = 0; i < 8; i++)
#pragma unroll
                for (int j = 0; j < 8; j++)
                    acc[i][j] = fmaf(av[i], bv[j], acc[i][j]);
        }
        __syncthreads();
    }

#pragma unroll
    for (int i = 0; i < 8; i++) {
        int r = row0 + ty * 8 + i;
        float bb = bias ? bias[(long long)z * sBias + r] : 0.f;
        float4 o0 = make_float4(acc[i][0] + bb, acc[i][1] + bb,
                                acc[i][2] + bb, acc[i][3] + bb);
        float4 o1 = make_float4(acc[i][4] + bb, acc[i][5] + bb,
                                acc[i][6] + bb, acc[i][7] + bb);
        *(float4*)&C[(long long)r * ldc + col0 + tx * 8]     = o0;
        *(float4*)&C[(long long)r * ldc + col0 + tx * 8 + 4] = o1;
    }
}

// ---------------------------------------------------------------------------
// s[b][c] = sum_n x[b][c][n]     — one block per (b,c) row
// ---------------------------------------------------------------------------
__global__ void rowsum_kernel(const float* __restrict__ x, float* __restrict__ s)
{
    const int row = blockIdx.x;                 // b*512 + c
    const float* p = x + (long long)row * N_;
    float acc = 0.f;
    for (int i = threadIdx.x; i < N_; i += 256) acc += p[i];
    __shared__ float sh[256];
    sh[threadIdx.x] = acc;
    __syncthreads();
    for (int st = 128; st > 0; st >>= 1) {
        if (threadIdx.x < st) sh[threadIdx.x] += sh[threadIdx.x + st];
        __syncthreads();
    }
    if (threadIdx.x == 0) s[row] = sh[0];
}

// ---------------------------------------------------------------------------
// t[b][e] = dot(w_qkv[e,:], s[b,:])   — one warp per (e, b)
// grid = 3072 blocks, 256 threads (8 warps = 8 batches)
// ---------------------------------------------------------------------------
__global__ void tvec_kernel(const float* __restrict__ w,
                            const float* __restrict__ s,
                            float* __restrict__ t)
{
    const int e = blockIdx.x;
    const int b = threadIdx.x >> 5;
    const int lane = threadIdx.x & 31;
    const float* wr = w + (long long)e * C_;
    const float* sb = s + b * C_;
    float acc = 0.f;
    for (int i = lane; i < C_; i += 32) acc += wr[i] * sb[i];
    for (int o = 16; o; o >>= 1) acc += __shfl_xor_sync(0xffffffffu, acc, o);
    if (!lane) t[b * (3 * E_) + e] = acc;
}

// ---------------------------------------------------------------------------
// Softmax + sparsity mask over e, plus cvec = (masked probs) . bv
// One block of 128 threads per row (b,h,d). Adds qkv-bias logit corrections.
// ---------------------------------------------------------------------------
__global__ void softmax_kernel(float* __restrict__ att,
                               const float* __restrict__ tvec,
                               const float* __restrict__ bqkv,
                               const float* __restrict__ mask,
                               float* __restrict__ cvec)
{
    const int idx = blockIdx.x;          // b*1024 + h*128 + d
    const int d = idx & 127;
    const int h = (idx >> 7) & 7;
    const int b = idx >> 10;
    const int e = threadIdx.x;
    const long long base = (long long)idx * D_;

    const float bq = bqkv[h * D_ + d];
    const float bk = bqkv[E_ + h * D_ + e];
    const float qt = tvec[b * (3 * E_) + h * D_ + d];
    const float kt = tvec[b * (3 * E_) + E_ + h * D_ + e];

    float L = att[base + e] + bq * kt + bk * qt + (float)N_ * bq * bk;

    __shared__ float sh[128];
    sh[e] = L;
    __syncthreads();
    for (int st = 64; st; st >>= 1) {
        if (e < st) sh[e] = fmaxf(sh[e], sh[e + st]);
        __syncthreads();
    }
    const float mx = sh[0];
    __syncthreads();

    const float ex = expf(L - mx);
    sh[e] = ex;
    __syncthreads();
    for (int st = 64; st; st >>= 1) {
        if (e < st) sh[e] += sh[e + st];
        __syncthreads();
    }
    const float inv = 1.f / sh[0];
    __syncthreads();

    const float m = (mask[base + e] < 0.1f) ? 1.f : 0.f;
    const float p = ex * inv * m;
    att[base + e] = p;

    // cvec[b, h*128+d] = sum_e p * bv[e]
    sh[e] = p * bqkv[2 * E_ + h * D_ + e];
    __syncthreads();
    for (int st = 64; st; st >>= 1) {
        if (e < st) sh[e] += sh[e + st];
        __syncthreads();
    }
    if (!e) cvec[b * E_ + h * D_ + d] = sh[0];
}

// ---------------------------------------------------------------------------
// g[b][cc] = dot(w_out[cc,:], cvec[b,:]) + b_out[cc]
// grid = 512 blocks (cc), 256 threads (8 warps = 8 batches)
// ---------------------------------------------------------------------------
__global__ void gvec_kernel(const float* __restrict__ wout,
                            const float* __restrict__ cvec,
                            const float* __restrict__ bout,
                            float* __restrict__ g)
{
    const int cc = blockIdx.x;
    const int b = threadIdx.x >> 5;
    const int lane = threadIdx.x & 31;
    const float* wr = wout + (long long)cc * E_;
    const float* cv = cvec + b * E_;
    float acc = 0.f;
    for (int i = lane; i < E_; i += 32) acc += wr[i] * cv[i];
    for (int o = 16; o; o >>= 1) acc += __shfl_xor_sync(0xffffffffu, acc, o);
    if (!lane) g[b * C_ + cc] = acc + bout[cc];
}

// ---------------------------------------------------------------------------
// Launch
// ---------------------------------------------------------------------------
extern "C" void kernel_launch(void* const* d_in, const int* in_sizes, int n_in,
                              void* d_out, int out_size)
{
    const float* x     = (const float*)d_in[0];
    const float* w_qkv = (const float*)d_in[1];
    const float* b_qkv = (const float*)d_in[2];
    const float* w_out = (const float*)d_in[3];
    const float* b_out = (const float*)d_in[4];
    const float* mask  = (const float*)d_in[5];
    float* out = (float*)d_out;

    float *G, *s, *t, *A1, *att, *Mm, *cv, *F, *g;
    cudaGetSymbolAddress((void**)&G,  d_G);
    cudaGetSymbolAddress((void**)&s,  d_s);
    cudaGetSymbolAddress((void**)&t,  d_t);
    cudaGetSymbolAddress((void**)&A1, d_A1);
    cudaGetSymbolAddress((void**)&att, d_att);
    cudaGetSymbolAddress((void**)&Mm, d_M);
    cudaGetSymbolAddress((void**)&cv, d_cv);
    cudaGetSymbolAddress((void**)&F,  d_F);
    cudaGetSymbolAddress((void**)&g,  d_g);

    const long long CN = (long long)C_ * N_;   // 512*4096
    const long long CC = (long long)C_ * C_;   // 512*512
    const long long EC = (long long)E_ * C_;   // 1024*512
    const long long DC = (long long)D_ * C_;   // 128*512
    const long long DD = (long long)D_ * D_;   // 128*128

    // 1) row sums of x
    rowsum_kernel<<<B_ * C_, 256>>>(x, s);

    // 2) Gram: G[b] (512x512) = x[b] (512x4096) @ x[b]^T   [NT]
    sgemm<true><<<dim3(4, 4, B_), 256>>>(
        x, x, G, nullptr,
        N_, N_, N_, C_,
        CN, 0, CN, 0, CC, 0, 1);

    // 3) t = W_qkv @ s
    tvec_kernel<<<3 * E_, 256>>>(w_qkv, s, t);

    // 4) A1[b] (1024x512) = Wq (1024x512) @ G[b]           [NN]
    sgemm<false><<<dim3(4, 8, B_), 256>>>(
        w_qkv, G, A1, nullptr,
        C_, C_, C_, C_,
        0, 0, CC, 0, EC, 0, 1);

    // 5) logits[b,h] (128x128) = A1[b,h] (128x512) @ Wk_h^T  [NT], z = b*8+h
    sgemm<true><<<dim3(1, 1, B_ * H_), 256>>>(
        A1, w_qkv + (long long)E_ * C_, att, nullptr,
        C_, C_, C_, D_,
        EC, DC, 0, DC, DD, 0, H_);

    // 6) softmax + mask + cvec
    softmax_kernel<<<B_ * H_ * D_, 128>>>(att, t, b_qkv, mask, cv);

    // 7) M[b,h] (128x512) = att[b,h] (128x128) @ Wv_h (128x512)  [NN]
    sgemm<false><<<dim3(4, 1, B_ * H_), 256>>>(
        att, w_qkv + 2LL * E_ * C_, Mm, nullptr,
        D_, D_, C_, C_,
        (long long)H_ * DD, DD, 0, DC, DC, 0, H_);

    // 8) g = w_out @ cvec + b_out
    gvec_kernel<<<C_, 256>>>(w_out, cv, b_out, g);

    // 9) F[b] (512x512) = w_out (512x1024) @ M[b] (1024x512)     [NN]
    sgemm<false><<<dim3(4, 4, B_), 256>>>(
        w_out, Mm, F, nullptr,
        E_, E_, C_, C_,
        0, 0, EC, 0, CC, 0, 1);

    // 10) out[b] (512x4096) = F[b] @ x[b] + g[b][row]            [NN]
    sgemm<false><<<dim3(32, 4, B_), 256>>>(
        F, x, out, g,
        C_, C_, N_, N_,
        CC, 0, CN, 0, CN, C_, 1);
}

// round 2
// speedup vs baseline: 1.1803x; 1.1803x over previous
#include <cuda_runtime.h>

// Problem constants
#define B_ 8
#define C_ 512
#define N_ 4096
#define E_ 1024
#define H_ 8
#define D_ 128

// Scratch (device globals). G/F have 2x size for split-K partials,
// att has 4x for split-K partials.
__device__ float d_G  [2 * B_ * C_ * C_];      // Gram partials (16 MB)
__device__ float d_s  [B_ * C_];               // row sums of x
__device__ float d_t  [B_ * 3 * E_];           // W_qkv @ s
__device__ float d_A1 [B_ * E_ * C_];          // Wq @ G (16 MB)
__device__ float d_att[4 * B_ * H_ * D_ * D_]; // logit partials -> probs (16 MB)
__device__ float d_M  [B_ * E_ * C_];          // att @ Wv (16 MB)
__device__ float d_cv [B_ * E_];               // att @ bv
__device__ float d_F  [2 * B_ * C_ * C_];      // w_out @ M partials (16 MB)
__device__ float d_g  [B_ * C_];               // w_out @ cv + b_out

#define BM 128
#define BN 128
#define BK 16
#define PAD 4
#define LDS_A (BM + PAD)
#define LDS_B (BN + PAD)

// ---------------------------------------------------------------------------
// Tiled fp32 GEMM v2: conflict-free frags, smem double buffer, global prefetch,
// split-K. C[zz,part] = A[zz](M x Kp) * op(B[zz])(Kp x N) [+ bias if KSPLIT==1]
// zz = z/KSPLIT, part = z%KSPLIT; zo = zz/ZB, zi = zz%ZB.
// ---------------------------------------------------------------------------
template <bool TRANSB, int KSPLIT>
__global__ void __launch_bounds__(256, 2)
sgemm2(const float* __restrict__ A, const float* __restrict__ B,
       float* __restrict__ C, const float* __restrict__ bias,
       int K, int lda, int ldb, int ldc,
       long long sAo, long long sAi, long long sBo, long long sBi,
       long long sCo, long long sPart, long long sBias, int ZB)
{
    const int z    = blockIdx.z;
    const int zz   = z / KSPLIT;
    const int part = z - zz * KSPLIT;
    const int zo   = zz / ZB;
    const int zi   = zz - zo * ZB;
    A += zo * sAo + zi * sAi;
    B += zo * sBo + zi * sBi;
    C += (long long)zz * sCo + (long long)part * sPart;

    const int Kp   = K / KSPLIT;
    const int kbeg = part * Kp;
    const int kend = kbeg + Kp;

    __shared__ float As[2][BK][LDS_A];
    __shared__ float Bs[2][BK][LDS_B];

    const int tid  = threadIdx.x;
    const int row0 = blockIdx.y * BM;
    const int col0 = blockIdx.x * BN;

    // tile-load indices
    const int lr4 = tid >> 2;        // 0..63
    const int cg  = (tid & 3) * 4;   // 0,4,8,12
    const int bk_ = tid >> 5;        // 0..7 (NN B k-rows)
    const int bj  = (tid & 31) * 4;  // 0..124

    // fragment indices: 8 warps as 4x2, warp tile 32x64, thread 8x8 (4+4 split)
    const int w    = tid >> 5;
    const int wr   = w & 3;
    const int wc   = w >> 2;
    const int lane = tid & 31;
    const int ra   = wr * 32 + (lane >> 3) * 4;  // A rows: ra..+3, ra+16..+3
    const int cb   = wc * 64 + (lane & 7) * 4;   // B cols: cb..+3, cb+32..+3

    float acc[8][8];
#pragma unroll
    for (int i = 0; i < 8; i++)
#pragma unroll
        for (int j = 0; j < 8; j++) acc[i][j] = 0.f;

    float4 pa0, pa1, pb0, pb1;

#define LDG_TILE(KK)                                                          \
    do {                                                                      \
        pa0 = *(const float4*)&A[(long long)(row0 + lr4)      * lda + (KK) + cg]; \
        pa1 = *(const float4*)&A[(long long)(row0 + lr4 + 64) * lda + (KK) + cg]; \
        if (TRANSB) {                                                         \
            pb0 = *(const float4*)&B[(long long)(col0 + lr4)      * ldb + (KK) + cg]; \
            pb1 = *(const float4*)&B[(long long)(col0 + lr4 + 64) * ldb + (KK) + cg]; \
        } else {                                                              \
            pb0 = *(const float4*)&B[(long long)((KK) + bk_)     * ldb + col0 + bj]; \
            pb1 = *(const float4*)&B[(long long)((KK) + bk_ + 8) * ldb + col0 + bj]; \
        }                                                                     \
    } while (0)

#define STS_TILE(BUF)                                                         \
    do {                                                                      \
        As[BUF][cg + 0][lr4] = pa0.x; As[BUF][cg + 1][lr4] = pa0.y;           \
        As[BUF][cg + 2][lr4] = pa0.z; As[BUF][cg + 3][lr4] = pa0.w;           \
        As[BUF][cg + 0][lr4 + 64] = pa1.x; As[BUF][cg + 1][lr4 + 64] = pa1.y; \
        As[BUF][cg + 2][lr4 + 64] = pa1.z; As[BUF][cg + 3][lr4 + 64] = pa1.w; \
        if (TRANSB) {                                                         \
            Bs[BUF][cg + 0][lr4] = pb0.x; Bs[BUF][cg + 1][lr4] = pb0.y;       \
            Bs[BUF][cg + 2][lr4] = pb0.z; Bs[BUF][cg + 3][lr4] = pb0.w;       \
            Bs[BUF][cg + 0][lr4 + 64] = pb1.x; Bs[BUF][cg + 1][lr4 + 64] = pb1.y; \
            Bs[BUF][cg + 2][lr4 + 64] = pb1.z; Bs[BUF][cg + 3][lr4 + 64] = pb1.w; \
        } else {                                                              \
            *(float4*)&Bs[BUF][bk_][bj]     = pb0;                            \
            *(float4*)&Bs[BUF][bk_ + 8][bj] = pb1;                            \
        }                                                                     \
    } while (0)

    LDG_TILE(kbeg);
    STS_TILE(0);
    __syncthreads();

    int buf = 0;
    for (int kk = kbeg; kk < kend; kk += BK) {
        const bool has_next = (kk + BK) < kend;
        if (has_next) LDG_TILE(kk + BK);

#pragma unroll
        for (int k = 0; k < BK; k++) {
            float4 a0 = *(const float4*)&As[buf][k][ra];
            float4 a1 = *(const float4*)&As[buf][k][ra + 16];
            float4 b0 = *(const float4*)&Bs[buf][k][cb];
            float4 b1 = *(const float4*)&Bs[buf][k][cb + 32];
            float av[8] = {a0.x, a0.y, a0.z, a0.w, a1.x, a1.y, a1.z, a1.w};
            float bv[8] = {b0.x, b0.y, b0.z, b0.w, b1.x, b1.y, b1.z, b1.w};
#pragma unroll
            for (int i = 0; i < 8; i++)
#pragma unroll
                for (int j = 0; j < 8; j++)
                    acc[i][j] = fmaf(av[i], bv[j], acc[i][j]);
        }

        if (has_next) {
            STS_TILE(buf ^ 1);
            __syncthreads();
            buf ^= 1;
        }
    }

#pragma unroll
    for (int i = 0; i < 4; i++) {
        {
            int r = row0 + ra + i;
            float bb = (KSPLIT == 1 && bias) ? bias[(long long)zz * sBias + r] : 0.f;
            float4 o0 = make_float4(acc[i][0] + bb, acc[i][1] + bb,
                                    acc[i][2] + bb, acc[i][3] + bb);
            float4 o1 = make_float4(acc[i][4] + bb, acc[i][5] + bb,
                                    acc[i][6] + bb, acc[i][7] + bb);
            *(float4*)&C[(long long)r * ldc + col0 + cb]      = o0;
            *(float4*)&C[(long long)r * ldc + col0 + cb + 32] = o1;
        }
        {
            int r = row0 + ra + 16 + i;
            float bb = (KSPLIT == 1 && bias) ? bias[(long long)zz * sBias + r] : 0.f;
            float4 o0 = make_float4(acc[i + 4][0] + bb, acc[i + 4][1] + bb,
                                    acc[i + 4][2] + bb, acc[i + 4][3] + bb);
            float4 o1 = make_float4(acc[i + 4][4] + bb, acc[i + 4][5] + bb,
                                    acc[i + 4][6] + bb, acc[i + 4][7] + bb);
            *(float4*)&C[(long long)r * ldc + col0 + cb]      = o0;
            *(float4*)&C[(long long)r * ldc + col0 + cb + 32] = o1;
        }
    }
#undef LDG_TILE
#undef STS_TILE
}

// dst[i] += src[i]  (float4 granularity, n multiple of 4)
__global__ void add2_kernel(float* __restrict__ dst, const float* __restrict__ src,
                            long long n)
{
    long long i = ((long long)blockIdx.x * 256 + threadIdx.x) * 4;
    if (i < n) {
        float4 a = *(float4*)&dst[i];
        float4 b = *(const float4*)&src[i];
        a.x += b.x; a.y += b.y; a.z += b.z; a.w += b.w;
        *(float4*)&dst[i] = a;
    }
}

// ---------------------------------------------------------------------------
// s[b][c] = sum_n x[b][c][n]
// ---------------------------------------------------------------------------
__global__ void rowsum_kernel(const float* __restrict__ x, float* __restrict__ s)
{
    const int row = blockIdx.x;
    const float* p = x + (long long)row * N_;
    float acc = 0.f;
    for (int i = threadIdx.x; i < N_; i += 256) acc += p[i];
    __shared__ float sh[256];
    sh[threadIdx.x] = acc;
    __syncthreads();
    for (int st = 128; st > 0; st >>= 1) {
        if (threadIdx.x < st) sh[threadIdx.x] += sh[threadIdx.x + st];
        __syncthreads();
    }
    if (threadIdx.x == 0) s[row] = sh[0];
}

// t[b][e] = dot(w_qkv[e,:], s[b,:])
__global__ void tvec_kernel(const float* __restrict__ w,
                            const float* __restrict__ s,
                            float* __restrict__ t)
{
    const int e = blockIdx.x;
    const int b = threadIdx.x >> 5;
    const int lane = threadIdx.x & 31;
    const float* wr = w + (long long)e * C_;
    const float* sb = s + b * C_;
    float acc = 0.f;
    for (int i = lane; i < C_; i += 32) acc += wr[i] * sb[i];
    for (int o = 16; o; o >>= 1) acc += __shfl_xor_sync(0xffffffffu, acc, o);
    if (!lane) t[b * (3 * E_) + e] = acc;
}

// ---------------------------------------------------------------------------
// Softmax over e: sums 4 split-K logit partials, adds bias-logit terms,
// applies mask, writes probs to partial buffer 0, also computes cvec.
// ---------------------------------------------------------------------------
__global__ void softmax_kernel(float* __restrict__ att,
                               const float* __restrict__ tvec,
                               const float* __restrict__ bqkv,
                               const float* __restrict__ mask,
                               float* __restrict__ cvec)
{
    const int idx = blockIdx.x;          // b*1024 + h*128 + d
    const int d = idx & 127;
    const int h = (idx >> 7) & 7;
    const int b = idx >> 10;
    const int e = threadIdx.x;
    const long long base = (long long)idx * D_;
    const long long S = (long long)B_ * H_ * D_ * D_;

    const float bq = bqkv[h * D_ + d];
    const float bk = bqkv[E_ + h * D_ + e];
    const float qt = tvec[b * (3 * E_) + h * D_ + d];
    const float kt = tvec[b * (3 * E_) + E_ + h * D_ + e];

    float L = att[base + e] + att[S + base + e]
            + att[2 * S + base + e] + att[3 * S + base + e]
            + bq * kt + bk * qt + (float)N_ * bq * bk;

    __shared__ float sh[128];
    sh[e] = L;
    __syncthreads();
    for (int st = 64; st; st >>= 1) {
        if (e < st) sh[e] = fmaxf(sh[e], sh[e + st]);
        __syncthreads();
    }
    const float mx = sh[0];
    __syncthreads();

    const float ex = expf(L - mx);
    sh[e] = ex;
    __syncthreads();
    for (int st = 64; st; st >>= 1) {
        if (e < st) sh[e] += sh[e + st];
        __syncthreads();
    }
    const float inv = 1.f / sh[0];
    __syncthreads();

    const float m = (mask[base + e] < 0.1f) ? 1.f : 0.f;
    const float p = ex * inv * m;
    att[base + e] = p;

    sh[e] = p * bqkv[2 * E_ + h * D_ + e];
    __syncthreads();
    for (int st = 64; st; st >>= 1) {
        if (e < st) sh[e] += sh[e + st];
        __syncthreads();
    }
    if (!e) cvec[b * E_ + h * D_ + d] = sh[0];
}

// g[b][cc] = dot(w_out[cc,:], cvec[b,:]) + b_out[cc]
__global__ void gvec_kernel(const float* __restrict__ wout,
                            const float* __restrict__ cvec,
                            const float* __restrict__ bout,
                            float* __restrict__ g)
{
    const int cc = blockIdx.x;
    const int b = threadIdx.x >> 5;
    const int lane = threadIdx.x & 31;
    const float* wr = wout + (long long)cc * E_;
    const float* cv = cvec + b * E_;
    float acc = 0.f;
    for (int i = lane; i < E_; i += 32) acc += wr[i] * cv[i];
    for (int o = 16; o; o >>= 1) acc += __shfl_xor_sync(0xffffffffu, acc, o);
    if (!lane) g[b * C_ + cc] = acc + bout[cc];
}

// ---------------------------------------------------------------------------
// Launch
// ---------------------------------------------------------------------------
extern "C" void kernel_launch(void* const* d_in, const int* in_sizes, int n_in,
                              void* d_out, int out_size)
{
    const float* x     = (const float*)d_in[0];
    const float* w_qkv = (const float*)d_in[1];
    const float* b_qkv = (const float*)d_in[2];
    const float* w_out = (const float*)d_in[3];
    const float* b_out = (const float*)d_in[4];
    const float* mask  = (const float*)d_in[5];
    float* out = (float*)d_out;

    float *G, *s, *t, *A1, *att, *Mm, *cv, *F, *g;
    cudaGetSymbolAddress((void**)&G,  d_G);
    cudaGetSymbolAddress((void**)&s,  d_s);
    cudaGetSymbolAddress((void**)&t,  d_t);
    cudaGetSymbolAddress((void**)&A1, d_A1);
    cudaGetSymbolAddress((void**)&att, d_att);
    cudaGetSymbolAddress((void**)&Mm, d_M);
    cudaGetSymbolAddress((void**)&cv, d_cv);
    cudaGetSymbolAddress((void**)&F,  d_F);
    cudaGetSymbolAddress((void**)&g,  d_g);

    const long long CN = (long long)C_ * N_;
    const long long CC = (long long)C_ * C_;
    const long long EC = (long long)E_ * C_;
    const long long DC = (long long)D_ * C_;
    const long long DD = (long long)D_ * D_;
    const long long S  = (long long)B_ * H_ * DD;

    // 1) row sums of x
    rowsum_kernel<<<B_ * C_, 256>>>(x, s);

    // 2) Gram: G[b] = x[b] @ x[b]^T   [NT], split-K=2 -> 256 blocks
    sgemm2<true, 2><<<dim3(4, 4, 16), 256>>>(
        x, x, G, nullptr,
        N_, N_, N_, C_,
        CN, 0, CN, 0, CC, (long long)B_ * CC, 0, 1);
    add2_kernel<<<(int)((B_ * CC / 4 + 255) / 256), 256>>>(G, G + B_ * CC, B_ * CC);

    // 3) t = W_qkv @ s
    tvec_kernel<<<3 * E_, 256>>>(w_qkv, s, t);

    // 4) A1[b] = Wq @ G[b]   [NN]
    sgemm2<false, 1><<<dim3(4, 8, 8), 256>>>(
        w_qkv, G, A1, nullptr,
        C_, C_, C_, C_,
        0, 0, CC, 0, EC, 0, 0, 1);

    // 5) logits[b,h] = A1[b,h] @ Wk_h^T   [NT], split-K=4 -> 256 blocks
    sgemm2<true, 4><<<dim3(1, 1, 256), 256>>>(
        A1, w_qkv + (long long)E_ * C_, att, nullptr,
        C_, C_, C_, D_,
        EC, DC, 0, DC, DD, S, 0, H_);

    // 6) softmax (sums 4 partials) + mask + cvec
    softmax_kernel<<<B_ * H_ * D_, 128>>>(att, t, b_qkv, mask, cv);

    // 7) M[b,h] = att[b,h] @ Wv_h   [NN]
    sgemm2<false, 1><<<dim3(4, 1, 64), 256>>>(
        att, w_qkv + 2LL * E_ * C_, Mm, nullptr,
        D_, D_, C_, C_,
        (long long)H_ * DD, DD, 0, DC, DC, 0, 0, H_);

    // 8) g = w_out @ cvec + b_out
    gvec_kernel<<<C_, 256>>>(w_out, cv, b_out, g);

    // 9) F[b] = w_out @ M[b]   [NN], split-K=2 -> 256 blocks
    sgemm2<false, 2><<<dim3(4, 4, 16), 256>>>(
        w_out, Mm, F, nullptr,
        E_, E_, C_, C_,
        0, 0, EC, 0, CC, (long long)B_ * CC, 0, 1);
    add2_kernel<<<(int)((B_ * CC / 4 + 255) / 256), 256>>>(F, F + B_ * CC, B_ * CC);

    // 10) out[b] = F[b] @ x[b] + g[b][row]   [NN]
    sgemm2<false, 1><<<dim3(32, 4, 8), 256>>>(
        F, x, out, g,
        C_, C_, N_, N_,
        CC, 0, CN, 0, CN, 0, C_, 1);
}